// round 17
// baseline (speedup 1.0000x reference)
#include <cuda_runtime.h>
#include <math.h>

#define TT   512
#define BB   64
#define HH   300
#define KKT  9
#define G4   1200
#define NCOL 32768
#define HB   (HH*BB)
#define NSL  75
#define HROW 68
#define PROW 68
#define GMB  38              // gemm m-blocks of 64 rows

typedef unsigned long long ull;

__device__ __align__(16) float g_xT[(size_t)HH * NCOL];
__device__ __align__(16) float g_pre[(size_t)2 * G4 * NCOL];
__device__ __align__(16) float g_h[(size_t)2 * (TT + 1) * HB];
__device__ float g_emis[(size_t)TT * BB * KKT];
__device__ float g_bias[2 * G4];
__device__ float g_lossb[BB];
__device__ unsigned int g_bar2[64];
__device__ unsigned int g_flag[512];

__device__ __forceinline__ ull dup2(float v) {
    ull r; asm("mov.b64 %0, {%1, %1};" : "=l"(r) : "f"(v)); return r;
}
__device__ __forceinline__ ull fma2(ull a, ull b, ull c) {
    ull d; asm("fma.rn.f32x2 %0, %1, %2, %3;" : "=l"(d) : "l"(a), "l"(b), "l"(c)); return d;
}
__device__ __forceinline__ float2 u2f(ull v) {
    float2 r; asm("mov.b64 {%0, %1}, %2;" : "=f"(r.x), "=f"(r.y) : "l"(v)); return r;
}
__device__ __forceinline__ float sig_(float x) { return 1.0f / (1.0f + __expf(-x)); }
__device__ __forceinline__ float tanh_(float x) {
    float e = __expf(-2.0f * fabsf(x));
    float r = (1.0f - e) / (1.0f + e);
    return copysignf(r, x);
}
__device__ __forceinline__ unsigned int smem_u32(const void* p) {
    unsigned int a;
    asm("{ .reg .u64 t; cvta.to.shared.u64 t, %1; cvt.u32.u64 %0, t; }" : "=r"(a) : "l"(p));
    return a;
}
__device__ __forceinline__ void cpa16(unsigned int dst, const void* src) {
    asm volatile("cp.async.cg.shared.global [%0], [%1], 16;" :: "r"(dst), "l"(src) : "memory");
}
__device__ __forceinline__ void cpa16z(unsigned int dst, const void* src, int srcbytes) {
    asm volatile("cp.async.cg.shared.global [%0], [%1], 16, %2;"
                 :: "r"(dst), "l"(src), "r"(srcbytes) : "memory");
}
#define BARREC()  asm volatile("bar.sync 1, 384;" ::: "memory")
#define BARGEM()  asm volatile("bar.sync 2, 128;" ::: "memory")

// ---------------- K0: prep ----------------
__global__ void prep_kernel(const float* __restrict__ b_ih_f, const float* __restrict__ b_hh_f,
                            const float* __restrict__ b_ih_b, const float* __restrict__ b_hh_b,
                            const float* __restrict__ h0)
{
    int idx = blockIdx.x * blockDim.x + threadIdx.x;
    if (idx < 64) g_bar2[idx] = 0u;
    if (idx < 512) g_flag[idx] = 0u;
    if (idx < 2 * G4) {
        g_bias[idx] = (idx < G4) ? (b_ih_f[idx] + b_hh_f[idx])
                                 : (b_ih_b[idx - G4] + b_hh_b[idx - G4]);
    }
    if (idx < 2 * HB) {
        int dir = idx / HB;
        int rem = idx - dir * HB;
        int k = rem >> 6;
        int b = rem & 63;
        g_h[(size_t)dir * (TT + 1) * HB + (size_t)k * BB + b] = h0[(size_t)(dir * BB + b) * HH + k];
    }
}

// ---------------- K1: embedding gather ----------------
__global__ void gather_kernel(const int* __restrict__ tokens, const float* __restrict__ emb)
{
    extern __shared__ float xs[];
    __shared__ int tok[BB];
    const int t = blockIdx.x;
    const int tid = threadIdx.x;
    if (tid < BB) tok[tid] = tokens[tid * TT + t];
    __syncthreads();
    const int w = tid >> 5, lane = tid & 31;
#pragma unroll
    for (int i = 0; i < 8; i++) {
        int b = w * 8 + i;
        const float* er = emb + (size_t)tok[b] * HH;
        for (int d = lane; d < HH; d += 32) xs[b * 305 + d] = er[d];
    }
    __syncthreads();
    const int b = tid & 63;
    const int dbase = tid >> 6;
    float* dst = g_xT + (size_t)t * BB + b;
    for (int d = dbase; d < HH; d += 4)
        dst[(size_t)d * NCOL] = xs[b * 305 + d];
}

// ---------------- K2: FUSED persistent kernel: rec warps (0-11) + gemm warps (12-15) ----------------
// smem (floats): h_sm[300*68]=0..20400, part[192*68]=20400..33456,
// Wsm (2400 ull pairs)=33456..43056, As2 (2048 ull)=43056..47152, Bs(2048 f)=47152..49200
__global__ void __launch_bounds__(512, 1) fused_kernel(const float* __restrict__ whh_f,
                                                       const float* __restrict__ whh_b,
                                                       const float* __restrict__ wih_f,
                                                       const float* __restrict__ wih_b,
                                                       const float* __restrict__ c0)
{
    extern __shared__ __align__(16) float sm_f[];
    float* h_sm = sm_f;
    float* part = sm_f + 20400;
    ull*   Wsm  = (ull*)(sm_f + 33456);
    ull*   As2  = (ull*)(sm_f + 43056);     // [2][16][64]
    float* Bs   = sm_f + 47152;             // [2][16][64]

    const int bid = blockIdx.x;
    const int dir = bid & 1;
    const int s   = bid >> 1;
    const int colbase = s * 4;
    const int tid = threadIdx.x;

    // W_hh -> smem (all 512 threads), pairs [k*8+cgp][{c, c+2}]
    const float* whh = dir ? whh_b : whh_f;
    for (int idx = tid; idx < 2400; idx += 512) {
        int cgp = idx & 7, k = idx >> 3;
        int g = cgp & 3, ca = cgp >> 2;
        Wsm[idx * 2 + 0] = dup2(whh[(size_t)(g * HH + colbase + ca) * HH + k]);
        Wsm[idx * 2 + 1] = dup2(whh[(size_t)(g * HH + colbase + ca + 2) * HH + k]);
    }
    __syncthreads();     // last full-CTA barrier; roles diverge after this

    if (tid >= 384) {
        // ================= GEMM engine =================
        const int gt  = tid - 384;
        const int gty = gt >> 3;             // 0..15 -> 4 m rows
        const int gtx = gt & 7;              // 8 n cols (as 4 ull)
        const int glm = gt & 63;
        const int gka = (gt >> 6) * 8;
        const int gkb = gt >> 3;             // 0..15
        const int gnf = gt & 7;

        for (int q = bid; q < 512 * GMB; q += 2 * NSL) {
            const int nbi = q / GMB, mb = q - nbi * GMB;
            const int nb = (nbi & 1) ? (511 - (nbi >> 1)) : (nbi >> 1);
            const int m0 = mb * 64, n0 = nb * 64;
            const int am = m0 + glm;
            const bool amv = (am < 2400);
            const float* wrow = amv ? ((am < G4) ? (wih_f + (size_t)am * HH)
                                                 : (wih_b + (size_t)(am - G4) * HH))
                                    : (const float*)wih_f;
            ull acc[4][4];
#pragma unroll
            for (int i = 0; i < 4; i++)
#pragma unroll
                for (int j = 0; j < 4; j++) acc[i][j] = 0ull;

            float4 a0, a1;
            a0 = amv ? *(const float4*)(wrow + gka)     : make_float4(0,0,0,0);
            a1 = amv ? *(const float4*)(wrow + gka + 4) : make_float4(0,0,0,0);
            cpa16(smem_u32(&Bs[gkb * 64 + gnf * 4]),      g_xT + (size_t)gkb * NCOL + n0 + gnf * 4);
            cpa16(smem_u32(&Bs[gkb * 64 + gnf * 4 + 32]), g_xT + (size_t)gkb * NCOL + n0 + gnf * 4 + 32);
            asm volatile("cp.async.commit_group;" ::: "memory");
            As2[(gka + 0) * 64 + glm] = dup2(a0.x); As2[(gka + 1) * 64 + glm] = dup2(a0.y);
            As2[(gka + 2) * 64 + glm] = dup2(a0.z); As2[(gka + 3) * 64 + glm] = dup2(a0.w);
            As2[(gka + 4) * 64 + glm] = dup2(a1.x); As2[(gka + 5) * 64 + glm] = dup2(a1.y);
            As2[(gka + 6) * 64 + glm] = dup2(a1.z); As2[(gka + 7) * 64 + glm] = dup2(a1.w);
            asm volatile("cp.async.wait_group 0;" ::: "memory");
            BARGEM();

            int buf = 0;
            for (int ch = 1; ch < 19; ch++) {
                const int k0 = ch * 16;
                int ks0 = k0 + gka;
                int ks1 = (ks0 + 4 > 296) ? 296 : (ks0 + 4);   // clamp; zero-B kills garbage
                a0 = amv ? *(const float4*)(wrow + ks0) : make_float4(0,0,0,0);
                a1 = amv ? *(const float4*)(wrow + ks1) : make_float4(0,0,0,0);
                {
                    int kc = k0 + gkb;
                    int nbytes = (kc < 300) ? 16 : 0;
                    cpa16z(smem_u32(&Bs[((buf ^ 1) * 16 + gkb) * 64 + gnf * 4]),
                           g_xT + (size_t)kc * NCOL + n0 + gnf * 4, nbytes);
                    cpa16z(smem_u32(&Bs[((buf ^ 1) * 16 + gkb) * 64 + gnf * 4 + 32]),
                           g_xT + (size_t)kc * NCOL + n0 + gnf * 4 + 32, nbytes);
                }
                asm volatile("cp.async.commit_group;" ::: "memory");
#pragma unroll
                for (int kk = 0; kk < 16; kk++) {
                    const ull* ar = &As2[(buf * 16 + kk) * 64];
                    ulonglong2 avl = *(const ulonglong2*)(ar + gty * 4);
                    ulonglong2 avh = *(const ulonglong2*)(ar + gty * 4 + 2);
                    const ull* bsp = (const ull*)&Bs[(buf * 16 + kk) * 64];
                    ulonglong2 b01 = *(const ulonglong2*)(bsp + gtx * 4);
                    ulonglong2 b23 = *(const ulonglong2*)(bsp + gtx * 4 + 2);
                    acc[0][0]=fma2(avl.x,b01.x,acc[0][0]); acc[0][1]=fma2(avl.x,b01.y,acc[0][1]);
                    acc[0][2]=fma2(avl.x,b23.x,acc[0][2]); acc[0][3]=fma2(avl.x,b23.y,acc[0][3]);
                    acc[1][0]=fma2(avl.y,b01.x,acc[1][0]); acc[1][1]=fma2(avl.y,b01.y,acc[1][1]);
                    acc[1][2]=fma2(avl.y,b23.x,acc[1][2]); acc[1][3]=fma2(avl.y,b23.y,acc[1][3]);
                    acc[2][0]=fma2(avh.x,b01.x,acc[2][0]); acc[2][1]=fma2(avh.x,b01.y,acc[2][1]);
                    acc[2][2]=fma2(avh.x,b23.x,acc[2][2]); acc[2][3]=fma2(avh.x,b23.y,acc[2][3]);
                    acc[3][0]=fma2(avh.y,b01.x,acc[3][0]); acc[3][1]=fma2(avh.y,b01.y,acc[3][1]);
                    acc[3][2]=fma2(avh.y,b23.x,acc[3][2]); acc[3][3]=fma2(avh.y,b23.y,acc[3][3]);
                }
                ull* ad = &As2[(buf ^ 1) * 16 * 64];
                ad[(gka + 0) * 64 + glm] = dup2(a0.x); ad[(gka + 1) * 64 + glm] = dup2(a0.y);
                ad[(gka + 2) * 64 + glm] = dup2(a0.z); ad[(gka + 3) * 64 + glm] = dup2(a0.w);
                ad[(gka + 4) * 64 + glm] = dup2(a1.x); ad[(gka + 5) * 64 + glm] = dup2(a1.y);
                ad[(gka + 6) * 64 + glm] = dup2(a1.z); ad[(gka + 7) * 64 + glm] = dup2(a1.w);
                asm volatile("cp.async.wait_group 0;" ::: "memory");
                BARGEM();
                buf ^= 1;
            }
#pragma unroll
            for (int kk = 0; kk < 16; kk++) {
                const ull* ar = &As2[(buf * 16 + kk) * 64];
                ulonglong2 avl = *(const ulonglong2*)(ar + gty * 4);
                ulonglong2 avh = *(const ulonglong2*)(ar + gty * 4 + 2);
                const ull* bsp = (const ull*)&Bs[(buf * 16 + kk) * 64];
                ulonglong2 b01 = *(const ulonglong2*)(bsp + gtx * 4);
                ulonglong2 b23 = *(const ulonglong2*)(bsp + gtx * 4 + 2);
                acc[0][0]=fma2(avl.x,b01.x,acc[0][0]); acc[0][1]=fma2(avl.x,b01.y,acc[0][1]);
                acc[0][2]=fma2(avl.x,b23.x,acc[0][2]); acc[0][3]=fma2(avl.x,b23.y,acc[0][3]);
                acc[1][0]=fma2(avl.y,b01.x,acc[1][0]); acc[1][1]=fma2(avl.y,b01.y,acc[1][1]);
                acc[1][2]=fma2(avl.y,b23.x,acc[1][2]); acc[1][3]=fma2(avl.y,b23.y,acc[1][3]);
                acc[2][0]=fma2(avh.x,b01.x,acc[2][0]); acc[2][1]=fma2(avh.x,b01.y,acc[2][1]);
                acc[2][2]=fma2(avh.x,b23.x,acc[2][2]); acc[2][3]=fma2(avh.x,b23.y,acc[2][3]);
                acc[3][0]=fma2(avh.y,b01.x,acc[3][0]); acc[3][1]=fma2(avh.y,b01.y,acc[3][1]);
                acc[3][2]=fma2(avh.y,b23.x,acc[3][2]); acc[3][3]=fma2(avh.y,b23.y,acc[3][3]);
            }
#pragma unroll
            for (int i = 0; i < 4; i++) {
                int m = m0 + gty * 4 + i;
                if (m >= 2400) continue;
                float bvs = g_bias[m];
                float2 v0 = u2f(acc[i][0]), v1 = u2f(acc[i][1]);
                float2 v2 = u2f(acc[i][2]), v3 = u2f(acc[i][3]);
                float* cp = &g_pre[(size_t)m * NCOL + n0 + gtx * 8];
                ((float4*)cp)[0] = make_float4(v0.x + bvs, v0.y + bvs, v1.x + bvs, v1.y + bvs);
                ((float4*)cp)[1] = make_float4(v2.x + bvs, v2.y + bvs, v3.x + bvs, v3.y + bvs);
            }
            BARGEM();
            if (gt == 0)
                asm volatile("red.release.gpu.global.add.u32 [%0], 1;" :: "l"(&g_flag[nb]) : "memory");
        }
        return;
    }

    // ================= recurrence (384 threads, 12 warps) =================
    const int ks   = tid >> 5;               // 0..11, 25 k each (exact)
    const int lane = tid & 31;
    const int bq   = lane >> 3;
    const int cgrp = lane & 7;
    const int bqf  = (bq < 2) ? bq * 16 : 36 + (bq - 2) * 16;

    const int ffc = (tid >> 6) & 3;
    const int ffb = tid & 63;
    const int fcol = (ffb < 32) ? ffb : ffb + 4;
    float cst = 0.f;
    if (tid < 256) cst = c0[(size_t)(dir * BB + ffb) * HH + colbase + ffc];

    float*       ghdir  = g_h + (size_t)dir * (TT + 1) * HB;
    const float* predir = g_pre + (size_t)dir * G4 * NCOL;
    unsigned int* ctr   = &g_bar2[dir * 32];

    const unsigned int hdst0 = smem_u32(h_sm + (size_t)ks * 25 * HROW);
    const float* hbase = h_sm + (size_t)ks * 25 * HROW + bqf;
    const ull* Wp = Wsm + ((size_t)(ks * 25) * 8 + cgrp) * 2;
    float* ppA = part + (size_t)(ks * 16 + cgrp) * PROW + bqf;
    float* ppB = part + (size_t)(ks * 16 + cgrp + 8) * PROW + bqf;

    // wait for first timestep's pre-activations
    if (tid == 0) {
        const unsigned int* fl = &g_flag[dir ? 511 : 0];
        unsigned int f;
        do { asm volatile("ld.acquire.gpu.global.u32 %0, [%1];" : "=r"(f) : "l"(fl) : "memory"); }
        while (f < GMB);
    }
    BARREC();

    unsigned int target = 0;
    for (int t = 0; t < TT; t++) {
        const int tp = dir ? (TT - 1 - t) : t;

        float pre0 = 0.f, pre1 = 0.f, pre2 = 0.f, pre3 = 0.f;
        if (tid < 256) {
            const float* pb = predir + (size_t)tp * BB + ffb;
            pre0 = __ldcg(pb + (size_t)(0 * HH + colbase + ffc) * NCOL);
            pre1 = __ldcg(pb + (size_t)(1 * HH + colbase + ffc) * NCOL);
            pre2 = __ldcg(pb + (size_t)(2 * HH + colbase + ffc) * NCOL);
            pre3 = __ldcg(pb + (size_t)(3 * HH + colbase + ffc) * NCOL);
        }

        // stage h(t): 25 rows x 16 f4 per warp
        const float4* hsrc = (const float4*)(ghdir + (size_t)t * HB) + ks * 25 * 16;
#pragma unroll
        for (int j = 0; j < 12; j++) {
            int i = lane + 32 * j;
            unsigned int dst = hdst0 + (i >> 4) * (HROW * 4) + (i & 15) * 16 + ((i & 8) << 1);
            cpa16(dst, hsrc + i);
        }
        if (lane < 16) {
            int i = lane + 384;
            unsigned int dst = hdst0 + (i >> 4) * (HROW * 4) + (i & 15) * 16 + ((i & 8) << 1);
            cpa16(dst, hsrc + i);
        }
        asm volatile("cp.async.commit_group;" ::: "memory");
        asm volatile("cp.async.wait_group 0;" ::: "memory");
        __syncwarp();

        ull accA[8], accB[8];
#pragma unroll
        for (int i = 0; i < 8; i++) { accA[i] = 0ull; accB[i] = 0ull; }
#pragma unroll
        for (int kk = 0; kk < 25; kk++) {
            const ulonglong2* hp = (const ulonglong2*)(hbase + kk * HROW);
            ulonglong2 q0 = hp[0], q1 = hp[1], q2 = hp[2], q3 = hp[3];
            ulonglong2 w2 = *(const ulonglong2*)(Wp + (size_t)kk * 16);
            ull wA = w2.x, wB = w2.y;
            accA[0]=fma2(wA,q0.x,accA[0]); accA[1]=fma2(wA,q0.y,accA[1]);
            accA[2]=fma2(wA,q1.x,accA[2]); accA[3]=fma2(wA,q1.y,accA[3]);
            accA[4]=fma2(wA,q2.x,accA[4]); accA[5]=fma2(wA,q2.y,accA[5]);
            accA[6]=fma2(wA,q3.x,accA[6]); accA[7]=fma2(wA,q3.y,accA[7]);
            accB[0]=fma2(wB,q0.x,accB[0]); accB[1]=fma2(wB,q0.y,accB[1]);
            accB[2]=fma2(wB,q1.x,accB[2]); accB[3]=fma2(wB,q1.y,accB[3]);
            accB[4]=fma2(wB,q2.x,accB[4]); accB[5]=fma2(wB,q2.y,accB[5]);
            accB[6]=fma2(wB,q3.x,accB[6]); accB[7]=fma2(wB,q3.y,accB[7]);
        }
#pragma unroll
        for (int j = 0; j < 4; j++) {
            ulonglong2 v; v.x = accA[2 * j]; v.y = accA[2 * j + 1];
            *(ulonglong2*)(ppA + j * 4) = v;
        }
#pragma unroll
        for (int j = 0; j < 4; j++) {
            ulonglong2 v; v.x = accB[2 * j]; v.y = accB[2 * j + 1];
            *(ulonglong2*)(ppB + j * 4) = v;
        }
        BARREC();

        if (tid < 256) {
            float gv0 = pre0, gv1 = pre1, gv2 = pre2, gv3 = pre3;
#pragma unroll
            for (int kss = 0; kss < 12; kss++) {
                const float* pr = part + (size_t)(kss * 16 + ffc * 4) * PROW + fcol;
                gv0 += pr[0];
                gv1 += pr[PROW];
                gv2 += pr[2 * PROW];
                gv3 += pr[3 * PROW];
            }
            float ig = sig_(gv0), fg = sig_(gv1), gt = tanh_(gv2), og = sig_(gv3);
            cst = fg * cst + ig * gt;
            ghdir[(size_t)(t + 1) * HB + (size_t)(colbase + ffc) * BB + ffb] = og * tanh_(cst);
        }

        if (t == TT - 1) break;

        target += NSL;
        BARREC();
        if (tid == 0) {
            asm volatile("red.release.gpu.global.add.u32 [%0], 1;" :: "l"(ctr) : "memory");
            unsigned int v;
            do { asm volatile("ld.acquire.gpu.global.u32 %0, [%1];" : "=r"(v) : "l"(ctr) : "memory"); }
            while (v < target);
            const unsigned int* fl = &g_flag[dir ? (510 - t) : (t + 1)];
            unsigned int f;
            do { asm volatile("ld.acquire.gpu.global.u32 %0, [%1];" : "=r"(f) : "l"(fl) : "memory"); }
            while (f < GMB);
        }
        BARREC();
    }
}

// ---------------- K4: output projection (chunked smem staging) ----------------
#define PJC 75
__global__ void __launch_bounds__(288) proj_kernel(const float* __restrict__ w_out,
                                                   const float* __restrict__ b_out)
{
    extern __shared__ __align__(16) ull ws2[];
    float* hs = (float*)(ws2 + KKT * 2 * HH);
    const int t = blockIdx.x;
    const int tid = threadIdx.x;
    const int k = tid >> 5;
    const int bp = tid & 31;

    for (int i = tid; i < KKT * 2 * HH; i += 288) ws2[i] = dup2(w_out[i]);

    const float* hfg = g_h + (size_t)(t + 1) * HB;
    const float* hbg = g_h + (size_t)(TT + 1) * HB + (size_t)(TT - t) * HB;
    const ull* wk = ws2 + (size_t)k * (2 * HH);
    const ull* hp0 = (const ull*)hs + bp;

    ull acc[4];
    acc[0] = dup2(b_out[k]); acc[1] = 0ull; acc[2] = 0ull; acc[3] = 0ull;
#pragma unroll
    for (int c = 0; c < 4; c++) {
        __syncthreads();
        const float4* src = (const float4*)(hfg + (size_t)c * PJC * BB);
        for (int i = tid; i < PJC * 16; i += 288) ((float4*)hs)[i] = src[i];
        __syncthreads();
#pragma unroll 4
        for (int j = 0; j < PJC; j++) {
            int jj = c * PJC + j;
            acc[jj & 3] = fma2(wk[jj], hp0[j * 32], acc[jj & 3]);
        }
    }
#pragma unroll
    for (int c = 0; c < 4; c++) {
        __syncthreads();
        const float4* src = (const float4*)(hbg + (size_t)c * PJC * BB);
        for (int i = tid; i < PJC * 16; i += 288) ((float4*)hs)[i] = src[i];
        __syncthreads();
#pragma unroll 4
        for (int j = 0; j < PJC; j++) {
            int jj = c * PJC + j;
            acc[jj & 3] = fma2(wk[HH + jj], hp0[j * 32], acc[jj & 3]);
        }
    }
    float2 f0 = u2f(acc[0]), f1 = u2f(acc[1]), f2 = u2f(acc[2]), f3 = u2f(acc[3]);
    float rx = (f0.x + f1.x) + (f2.x + f3.x);
    float ry = (f0.y + f1.y) + (f2.y + f3.y);
    g_emis[(size_t)t * (BB * KKT) + (2 * bp) * KKT + k]     = rx;
    g_emis[(size_t)t * (BB * KKT) + (2 * bp + 1) * KKT + k] = ry;
}

// ---------------- K5: merged Viterbi + CRF ----------------
__global__ void vitcrf_kernel(const int* __restrict__ tags,
                              const float* __restrict__ start_t, const float* __restrict__ end_t,
                              const float* __restrict__ trans, float* __restrict__ out)
{
    const int b = blockIdx.x & 63;
    const int k = threadIdx.x;
    __shared__ float sc[KKT], ns[KKT], tr[KKT * KKT];
    __shared__ int hist_s[(TT - 1) * KKT];
    for (int i = k; i < KKT * KKT; i += 32) tr[i] = trans[i];
    __syncwarp();

    if (blockIdx.x < BB) {
        if (k < KKT) sc[k] = start_t[k] + g_emis[(size_t)b * KKT + k];
        float enext = (k < KKT) ? __ldcg(&g_emis[(size_t)(BB + b) * KKT + k]) : 0.f;
        __syncwarp();
        for (int t = 1; t < TT; t++) {
            float ecur = enext;
            if (k < KKT && t + 1 < TT)
                enext = __ldcg(&g_emis[((size_t)(t + 1) * BB + b) * KKT + k]);
            if (k < KKT) {
                float best = -1e30f; int arg = 0;
#pragma unroll
                for (int kp = 0; kp < KKT; kp++) {
                    float v = sc[kp] + tr[kp * KKT + k];
                    if (v > best) { best = v; arg = kp; }
                }
                ns[k] = best + ecur;
                hist_s[(t - 1) * KKT + k] = arg;
            }
            __syncwarp();
            if (k < KKT) sc[k] = ns[k];
            __syncwarp();
        }
        if (k == 0) {
            float best = -1e30f; int last = 0;
#pragma unroll
            for (int kk = 0; kk < KKT; kk++) {
                float v = sc[kk] + end_t[kk];
                if (v > best) { best = v; last = kk; }
            }
            out[(size_t)b * TT + (TT - 1)] = (float)last;
            int tag = last;
            for (int t = TT - 2; t >= 0; t--) {
                tag = hist_s[t * KKT + tag];
                out[(size_t)b * TT + t] = (float)tag;
            }
        }
    } else {
        float partn = 0.f;
        for (int t = k; t < TT; t += 32) {
            int ttg = tags[(size_t)b * TT + t];
            if (t == 0) partn += start_t[ttg] + g_emis[(size_t)b * KKT + ttg];
            else {
                int tp = tags[(size_t)b * TT + t - 1];
                partn += tr[tp * KKT + ttg] + g_emis[((size_t)t * BB + b) * KKT + ttg];
            }
            if (t == TT - 1) partn += end_t[ttg];
        }
#pragma unroll
        for (int off = 16; off; off >>= 1)
            partn += __shfl_xor_sync(0xffffffffu, partn, off);
        float num = partn;

        if (k < KKT) sc[k] = start_t[k] + g_emis[(size_t)b * KKT + k];
        float enext = (k < KKT) ? __ldcg(&g_emis[(size_t)(BB + b) * KKT + k]) : 0.f;
        __syncwarp();
        for (int t = 1; t < TT; t++) {
            float ecur = enext;
            if (k < KKT && t + 1 < TT)
                enext = __ldcg(&g_emis[((size_t)(t + 1) * BB + b) * KKT + k]);
            if (k < KKT) {
                float mx = -1e30f;
#pragma unroll
                for (int kp = 0; kp < KKT; kp++) mx = fmaxf(mx, sc[kp] + tr[kp * KKT + k]);
                float ssum = 0.f;
#pragma unroll
                for (int kp = 0; kp < KKT; kp++) ssum += expf(sc[kp] + tr[kp * KKT + k] - mx);
                ns[k] = mx + logf(ssum) + ecur;
            }
            __syncwarp();
            if (k < KKT) sc[k] = ns[k];
            __syncwarp();
        }
        if (k == 0) {
            float mx = -1e30f;
#pragma unroll
            for (int kk = 0; kk < KKT; kk++) mx = fmaxf(mx, sc[kk] + end_t[kk]);
            float ssum = 0.f;
#pragma unroll
            for (int kk = 0; kk < KKT; kk++) ssum += expf(sc[kk] + end_t[kk] - mx);
            g_lossb[b] = (mx + logf(ssum)) - num;
        }
    }
}

// ---------------- K6: deterministic loss reduction ----------------
__global__ void finalize_kernel(float* __restrict__ out)
{
    if (blockIdx.x == 0 && threadIdx.x == 0) {
        float s = 0.f;
        for (int b = 0; b < BB; b++) s += g_lossb[b];
        out[(size_t)BB * TT] = s;
    }
}

// ---------------- launch ----------------
extern "C" void kernel_launch(void* const* d_in, const int* in_sizes, int n_in,
                              void* d_out, int out_size)
{
    const int*   tokens  = (const int*)  d_in[0];
    const int*   tags    = (const int*)  d_in[1];
    const float* emb     = (const float*)d_in[3];
    const float* w_ih_f  = (const float*)d_in[4];
    const float* w_hh_f  = (const float*)d_in[5];
    const float* b_ih_f  = (const float*)d_in[6];
    const float* b_hh_f  = (const float*)d_in[7];
    const float* w_ih_b  = (const float*)d_in[8];
    const float* w_hh_b  = (const float*)d_in[9];
    const float* b_ih_b  = (const float*)d_in[10];
    const float* b_hh_b  = (const float*)d_in[11];
    const float* h0      = (const float*)d_in[12];
    const float* c0      = (const float*)d_in[13];
    const float* w_out   = (const float*)d_in[14];
    const float* b_out   = (const float*)d_in[15];
    const float* start_t = (const float*)d_in[16];
    const float* end_t   = (const float*)d_in[17];
    const float* trans   = (const float*)d_in[18];
    float* out = (float*)d_out;

    const int fused_smem  = 49200 * 4;                       // 196800 bytes
    const int gather_smem = 64 * 305 * 4;
    const int proj_smem   = KKT * 2 * HH * 8 + PJC * 64 * 4;
    static int smem_set = 0;
    if (!smem_set) {
        cudaFuncSetAttribute(fused_kernel, cudaFuncAttributeMaxDynamicSharedMemorySize, fused_smem);
        cudaFuncSetAttribute(gather_kernel, cudaFuncAttributeMaxDynamicSharedMemorySize, gather_smem);
        cudaFuncSetAttribute(proj_kernel, cudaFuncAttributeMaxDynamicSharedMemorySize, proj_smem);
        smem_set = 1;
    }

    prep_kernel<<<150, 256>>>(b_ih_f, b_hh_f, b_ih_b, b_hh_b, h0);
    gather_kernel<<<TT, 256, gather_smem>>>(tokens, emb);
    fused_kernel<<<2 * NSL, 512, fused_smem>>>(w_hh_f, w_hh_b, w_ih_f, w_ih_b, c0);
    proj_kernel<<<TT, 288, proj_smem>>>(w_out, b_out);
    vitcrf_kernel<<<2 * BB, 32>>>(tags, start_t, end_t, trans, out);
    finalize_kernel<<<1, 1>>>(out);
}